// round 4
// baseline (speedup 1.0000x reference)
#include <cuda_runtime.h>

#define DPRED   84
#define NCLS    80
#define MAXB    8
#define MAXA    76725
#define NBINS   4096
#define KMAX    1024
#define KTARGET 200
#define MAXDET  100
#define CONF_T  0.05f
#define IOU_T   0.5f
#define NT      512

// ---------------- device scratch (no allocation allowed) ----------------
// 8 floats per anchor: cx,cy,w,h,cls,conf,pad,pad  (aligned float4 pairs)
__device__ float4 g_boxes8[MAXB * MAXA * 2];
__device__ float  g_scores[MAXB * MAXA];      // conf if >= CONF_T else 0
__device__ float  g_thresh[MAXB];
__device__ int    g_cnt[MAXB];
__device__ int    g_cand[MAXB * KMAX];

// ---------------- decode: warp per anchor ----------------
__global__ void decode_kernel(const float* __restrict__ pred,
                              const float* __restrict__ anchors,
                              int B, int A) {
    int gw   = (blockIdx.x * blockDim.x + threadIdx.x) >> 5;
    int lane = threadIdx.x & 31;
    if (gw >= B * A) return;
    int a = gw % A;

    const float* row = pred + (size_t)gw * DPRED;
    float4 v = make_float4(-3.4e38f, -3.4e38f, -3.4e38f, -3.4e38f);
    if (lane < DPRED / 4)
        v = __ldg(reinterpret_cast<const float4*>(row) + lane);

    // per-lane argmax over class logits (j >= 4), first-occurrence ties
    float best = -3.4e38f;
    int   bi   = 1 << 30;
    float vv[4] = {v.x, v.y, v.z, v.w};
    int j0 = lane * 4;
#pragma unroll
    for (int t = 0; t < 4; t++) {
        int j = j0 + t;
        if (j >= 4 && vv[t] > best) { best = vv[t]; bi = j - 4; }
    }
#pragma unroll
    for (int off = 16; off; off >>= 1) {
        float ob = __shfl_down_sync(0xffffffffu, best, off);
        int   oi = __shfl_down_sync(0xffffffffu, bi, off);
        if (ob > best || (ob == best && oi < bi)) { best = ob; bi = oi; }
    }

    if (lane == 0) {
        float4 an = __ldg(reinterpret_cast<const float4*>(anchors) + a);
        float cx = v.x * 0.1f * an.z + an.x;
        float cy = v.y * 0.1f * an.w + an.y;
        float w  = expf(v.z * 0.2f) * an.z;
        float h  = expf(v.w * 0.2f) * an.w;
        float conf = 1.0f / (1.0f + expf(-best));
        g_boxes8[(size_t)gw * 2 + 0] = make_float4(cx, cy, w, h);
        g_boxes8[(size_t)gw * 2 + 1] = make_float4((float)bi, conf, 0.f, 0.f);
        g_scores[gw] = (conf >= CONF_T) ? conf : 0.0f;
    }
}

// ---------------- fused histogram + threshold: one block per batch --------
__global__ void __launch_bounds__(NT)
hist_thresh_kernel(int A) {
    __shared__ int sh[NBINS];
    __shared__ int csum[NT];           // 8-bin chunk sums
    int b   = blockIdx.x;
    int tid = threadIdx.x;

    for (int i = tid; i < NBINS; i += NT) sh[i] = 0;
    __syncthreads();

    const float* sc = g_scores + (size_t)b * A;
    for (int i = tid; i < A; i += NT) {
        float s = sc[i];
        if (s > 0.0f) {
            int bin = (int)(s * (float)NBINS);
            if (bin > NBINS - 1) bin = NBINS - 1;
            if (bin < 1) bin = 1;
            atomicAdd(&sh[bin], 1);
        }
    }
    __syncthreads();

    {   // 8 bins per chunk
        int s = 0;
        int base = tid * 8;
#pragma unroll
        for (int j = 0; j < 8; j++) s += sh[base + j];
        csum[tid] = s;
    }
    __syncthreads();

    if (tid == 0) {
        int cum = 0, binSel = NBINS, c = NT;
        while (c > 1 && cum < KTARGET && cum + csum[c - 1] <= KMAX) {
            c--; cum += csum[c]; binSel = c * 8;
        }
        if (cum < KTARGET && c >= 1) {
            for (int bin = c * 8 - 1; bin >= (c - 1) * 8 && bin >= 1; --bin) {
                int h = sh[bin];
                if (cum + h > KMAX) break;
                cum += h; binSel = bin;
                if (cum >= KTARGET) break;
            }
        }
        g_thresh[b] = (float)binSel / (float)NBINS;
        g_cnt[b]    = 0;
    }
}

// ---------------- compact candidates ----------------
__global__ void compact_kernel(int A) {
    int b = blockIdx.y;
    float th = g_thresh[b];
    const float* sc = g_scores + (size_t)b * A;
    for (int i = blockIdx.x * blockDim.x + threadIdx.x; i < A;
         i += gridDim.x * blockDim.x) {
        if (sc[i] > th) {
            int p = atomicAdd(&g_cnt[b], 1);
            if (p < KMAX) g_cand[b * KMAX + p] = i;
        }
    }
}

// ---------------- NMS: block per batch, single-warp fast path ------------
__global__ void __launch_bounds__(NT, 1)
nms_kernel(float* __restrict__ out, int A) {
    int b   = blockIdx.x;
    int tid = threadIdx.x;

    __shared__ unsigned long long skey[KMAX];
    __shared__ float sx1[KMAX], sy1[KMAX], sx2[KMAX], sy2[KMAX], sar[KMAX];
    __shared__ int   scls[KMAX];
    __shared__ unsigned long long sBest;
    __shared__ int sFallback;
    __shared__ unsigned long long redk[NT / 32];

    int cnt = g_cnt[b];
    bool overflow = (cnt > KMAX);
    if (cnt > KMAX) cnt = KMAX;

    for (int i = tid; i < cnt; i += NT) {
        int a = g_cand[b * KMAX + i];
        size_t base = ((size_t)b * A + a) * 2;
        float4 p0 = g_boxes8[base + 0];
        float4 p1 = g_boxes8[base + 1];
        float hw = 0.5f * p0.z, hh = 0.5f * p0.w;
        sx1[i] = p0.x - hw; sy1[i] = p0.y - hh;
        sx2[i] = p0.x + hw; sy2[i] = p0.y + hh;
        sar[i] = p0.z * p0.w;
        scls[i] = (int)p1.x;
        skey[i] = ((unsigned long long)__float_as_uint(p1.y) << 32) |
                  (unsigned)(0x7FFFFFFF - a);
    }
    if (tid == 0) sFallback = overflow ? 1 : 0;
    __syncthreads();

    // ---- fast path: warp 0 only, no block barriers ----
    if (tid < 32 && !sFallback) {
        int lane = tid;
        for (int d = 0; d < MAXDET; d++) {
            unsigned long long lk = 0; int ls = -1;
            for (int i = lane; i < cnt; i += 32) {
                unsigned long long k = skey[i];
                if (k > lk) { lk = k; ls = i; }
            }
            if (lane == 0) sBest = 0;
            __syncwarp();
            if (lk) atomicMax(&sBest, lk);
            __syncwarp();
            unsigned long long selKey = sBest;
            float selScore = __uint_as_float((unsigned)(selKey >> 32));
            if (selScore <= 0.0f) {
                if (lane == 0) sFallback = 1;   // pool exhausted -> exact path
                break;
            }
            // resolve winning slot via ballot (keys are unique: idx in low bits)
            unsigned winMask = __ballot_sync(0xffffffffu, lk == selKey);
            int winLane = __ffs(winMask) - 1;
            int sl = __shfl_sync(0xffffffffu, ls, winLane);

            float X1 = sx1[sl], Y1 = sy1[sl], X2 = sx2[sl], Y2 = sy2[sl];
            float AR = sar[sl];
            int   CL = scls[sl];

            if (lane == 0) {
                float w = X2 - X1, h = Y2 - Y1;
                float* o = out + ((size_t)b * MAXDET + d) * 6;
                o[0] = X1 + 0.5f * w; o[1] = Y1 + 0.5f * h;
                o[2] = w; o[3] = h;
                o[4] = (float)CL; o[5] = selScore;
            }
            for (int i = lane; i < cnt; i += 32) {
                if (i == sl) { skey[i] = 0; continue; }
                if (scls[i] == CL && skey[i] != 0ull) {
                    float iw = fminf(sx2[i], X2) - fmaxf(sx1[i], X1);
                    float ih = fminf(sy2[i], Y2) - fmaxf(sy1[i], Y1);
                    if (iw > 0.0f && ih > 0.0f) {
                        float inter = iw * ih;
                        float iou = inter / (sar[i] + AR - inter + 1e-8f);
                        if (iou > IOU_T) skey[i] = 0;
                    }
                }
            }
            __syncwarp();
        }
    }
    __syncthreads();

    // ---------------- exact full-array fallback (normally unreachable) ----
    if (sFallback) {
        float* sc = g_scores + (size_t)b * A;
        const float4* bx = g_boxes8 + (size_t)b * A * 2;
        for (int d = 0; d < MAXDET; d++) {
            unsigned long long mk = 0;
            for (int i = tid; i < A; i += NT) {
                unsigned long long k =
                    ((unsigned long long)__float_as_uint(sc[i]) << 32) |
                    (unsigned)(0x7FFFFFFF - i);
                if (k > mk) mk = k;
            }
#pragma unroll
            for (int off = 16; off; off >>= 1) {
                unsigned long long ok = __shfl_down_sync(0xffffffffu, mk, off);
                if (ok > mk) mk = ok;
            }
            if ((tid & 31) == 0) redk[tid >> 5] = mk;
            __syncthreads();
            if (tid < 32) {
                unsigned long long k2 = (tid < NT / 32) ? redk[tid] : 0ull;
#pragma unroll
                for (int off = 16; off; off >>= 1) {
                    unsigned long long ok = __shfl_down_sync(0xffffffffu, k2, off);
                    if (ok > k2) k2 = ok;
                }
                if (tid == 0) sBest = k2;
            }
            __syncthreads();
            unsigned long long selKey = sBest;
            int   a = 0x7FFFFFFF - (int)(selKey & 0xFFFFFFFFull);
            float selScore = __uint_as_float((unsigned)(selKey >> 32));
            float4 p0 = bx[(size_t)a * 2 + 0];
            float4 p1 = bx[(size_t)a * 2 + 1];
            float X1 = p0.x - 0.5f * p0.z, Y1 = p0.y - 0.5f * p0.w;
            float X2 = p0.x + 0.5f * p0.z, Y2 = p0.y + 0.5f * p0.w;
            float AR = p0.z * p0.w;
            int   CL = (int)p1.x;
            if (tid == 0) {
                float* o = out + ((size_t)b * MAXDET + d) * 6;
                o[0] = p0.x; o[1] = p0.y; o[2] = p0.z;
                o[3] = p0.w; o[4] = p1.x; o[5] = selScore;
            }
            __syncthreads();
            for (int i = tid; i < A; i += NT) {
                if (i == a) { sc[i] = 0.0f; continue; }
                if (sc[i] == 0.0f) continue;
                float4 q0 = bx[(size_t)i * 2 + 0];
                float4 q1 = bx[(size_t)i * 2 + 1];
                if ((int)q1.x == CL) {
                    float iw = fminf(q0.x + 0.5f * q0.z, X2) - fmaxf(q0.x - 0.5f * q0.z, X1);
                    float ih = fminf(q0.y + 0.5f * q0.w, Y2) - fmaxf(q0.y - 0.5f * q0.w, Y1);
                    if (iw > 0.0f && ih > 0.0f) {
                        float inter = iw * ih;
                        float iou = inter / (q0.z * q0.w + AR - inter + 1e-8f);
                        if (iou > IOU_T) sc[i] = 0.0f;
                    }
                }
            }
            __syncthreads();
        }
    }
}

// ---------------- launch ----------------
extern "C" void kernel_launch(void* const* d_in, const int* in_sizes, int n_in,
                              void* d_out, int out_size) {
    const float *pred, *anch;
    int s0 = in_sizes[0], s1 = in_sizes[1];
    if (s0 >= s1) {
        pred = (const float*)d_in[0]; anch = (const float*)d_in[1];
    } else {
        pred = (const float*)d_in[1]; anch = (const float*)d_in[0];
        int t = s0; s0 = s1; s1 = t;
    }
    int A = s1 / 4;
    int B = out_size / (MAXDET * 6);

    int totalWarps = B * A;
    decode_kernel<<<(totalWarps + 7) / 8, 256>>>(pred, anch, B, A);
    hist_thresh_kernel<<<B, NT>>>(A);
    compact_kernel<<<dim3(16, B), 256>>>(A);
    nms_kernel<<<B, NT>>>((float*)d_out, A);
}

// round 5
// speedup vs baseline: 1.1700x; 1.1700x over previous
#include <cuda_runtime.h>

#define DPRED    84
#define NCLS     80
#define MAXB     8
#define MAXA     76725
#define NBINS    4096
#define KMAX     512
#define KTARGET  128
#define PER_LANE (KMAX / 32)
#define MAXDET   100
#define CONF_T   0.05f
#define IOU_T    0.5f
#define HT_NT    512
#define NMS_NT   256

typedef unsigned long long u64;

// ---------------- device scratch (no allocation allowed) ----------------
__device__ float4 g_boxes8[MAXB * MAXA * 2];  // cx,cy,w,h | cls,conf,0,0
__device__ float  g_scores[MAXB * MAXA];      // conf if >= CONF_T else 0
__device__ int    g_cnt[MAXB];
__device__ int    g_cand[MAXB * KMAX];

// ---------------- decode: warp per anchor ----------------
__global__ void decode_kernel(const float* __restrict__ pred,
                              const float* __restrict__ anchors,
                              int B, int A) {
    int gw   = (blockIdx.x * blockDim.x + threadIdx.x) >> 5;
    int lane = threadIdx.x & 31;
    if (gw >= B * A) return;
    int a = gw % A;

    const float* row = pred + (size_t)gw * DPRED;
    float4 v = make_float4(-3.4e38f, -3.4e38f, -3.4e38f, -3.4e38f);
    if (lane < DPRED / 4)
        v = __ldg(reinterpret_cast<const float4*>(row) + lane);

    // per-lane argmax over class logits (j >= 4), first-occurrence ties
    float best = -3.4e38f;
    int   bi   = 1 << 30;
    float vv[4] = {v.x, v.y, v.z, v.w};
    int j0 = lane * 4;
#pragma unroll
    for (int t = 0; t < 4; t++) {
        int j = j0 + t;
        if (j >= 4 && vv[t] > best) { best = vv[t]; bi = j - 4; }
    }
#pragma unroll
    for (int off = 16; off; off >>= 1) {
        float ob = __shfl_down_sync(0xffffffffu, best, off);
        int   oi = __shfl_down_sync(0xffffffffu, bi, off);
        if (ob > best || (ob == best && oi < bi)) { best = ob; bi = oi; }
    }

    if (lane == 0) {
        float4 an = __ldg(reinterpret_cast<const float4*>(anchors) + a);
        float cx = v.x * 0.1f * an.z + an.x;
        float cy = v.y * 0.1f * an.w + an.y;
        float w  = expf(v.z * 0.2f) * an.z;
        float h  = expf(v.w * 0.2f) * an.w;
        float conf = 1.0f / (1.0f + expf(-best));
        g_boxes8[(size_t)gw * 2 + 0] = make_float4(cx, cy, w, h);
        g_boxes8[(size_t)gw * 2 + 1] = make_float4((float)bi, conf, 0.f, 0.f);
        g_scores[gw] = (conf >= CONF_T) ? conf : 0.0f;
    }
}

// -------- fused histogram + threshold + compaction: block per batch ------
__global__ void __launch_bounds__(HT_NT)
hist_compact_kernel(int A) {
    __shared__ int   sh[NBINS];
    __shared__ int   csum[HT_NT];      // 8-bin chunk sums
    __shared__ float sth;
    __shared__ int   sctr;
    int b   = blockIdx.x;
    int tid = threadIdx.x;

    for (int i = tid; i < NBINS; i += HT_NT) sh[i] = 0;
    if (tid == 0) sctr = 0;
    __syncthreads();

    const float* sc = g_scores + (size_t)b * A;
    for (int i = tid; i < A; i += HT_NT) {
        float s = sc[i];
        if (s > 0.0f) {
            int bin = (int)(s * (float)NBINS);
            if (bin > NBINS - 1) bin = NBINS - 1;
            if (bin < 1) bin = 1;
            atomicAdd(&sh[bin], 1);
        }
    }
    __syncthreads();

    {   // 8 bins per chunk
        int s = 0;
        int base = tid * 8;
#pragma unroll
        for (int j = 0; j < 8; j++) s += sh[base + j];
        csum[tid] = s;
    }
    __syncthreads();

    if (tid == 0) {
        int cum = 0, binSel = NBINS, c = HT_NT;
        while (c > 1 && cum < KTARGET && cum + csum[c - 1] <= KMAX) {
            c--; cum += csum[c]; binSel = c * 8;
        }
        if (cum < KTARGET && c >= 1) {
            for (int bin = c * 8 - 1; bin >= (c - 1) * 8 && bin >= 1; --bin) {
                int h = sh[bin];
                if (cum + h > KMAX) break;
                cum += h; binSel = bin;
                if (cum >= KTARGET) break;
            }
        }
        sth = (float)binSel / (float)NBINS;
    }
    __syncthreads();

    float th = sth;
    for (int i = tid; i < A; i += HT_NT) {
        if (sc[i] > th) {
            int p = atomicAdd(&sctr, 1);
            if (p < KMAX) g_cand[b * KMAX + p] = i;
        }
    }
    __syncthreads();
    if (tid == 0) g_cnt[b] = sctr;
}

// ---------------- NMS: block per batch, register-resident warp 0 --------
__global__ void __launch_bounds__(NMS_NT, 1)
nms_kernel(float* __restrict__ out, int A) {
    int b   = blockIdx.x;
    int tid = threadIdx.x;

    __shared__ u64   skey[KMAX];
    __shared__ float sx1[KMAX], sy1[KMAX], sx2[KMAX], sy2[KMAX], sar[KMAX];
    __shared__ float scx[KMAX], scy[KMAX], swd[KMAX], sht[KMAX];
    __shared__ int   scls[KMAX];
    __shared__ int   sFallback;
    __shared__ u64   sBest;
    __shared__ u64   redk[NMS_NT / 32];

    int cnt = g_cnt[b];
    bool overflow = (cnt > KMAX);
    if (cnt > KMAX) cnt = KMAX;

    for (int i = tid; i < cnt; i += NMS_NT) {
        int a = g_cand[b * KMAX + i];
        size_t base = ((size_t)b * A + a) * 2;
        float4 p0 = g_boxes8[base + 0];
        float4 p1 = g_boxes8[base + 1];
        float hw = 0.5f * p0.z, hh = 0.5f * p0.w;
        sx1[i] = p0.x - hw; sy1[i] = p0.y - hh;
        sx2[i] = p0.x + hw; sy2[i] = p0.y + hh;
        sar[i] = p0.z * p0.w;
        scx[i] = p0.x; scy[i] = p0.y; swd[i] = p0.z; sht[i] = p0.w;
        scls[i] = (int)p1.x;
        skey[i] = ((u64)__float_as_uint(p1.y) << 32) |
                  (unsigned)(0x7FFFFFFF - a);
    }
    if (tid == 0) sFallback = overflow ? 1 : 0;
    __syncthreads();

    // ---- fast path: warp 0, all candidates in registers, no barriers ----
    if (tid < 32 && !sFallback) {
        int lane = tid;
        u64   kk[PER_LANE];
        float rx1[PER_LANE], ry1[PER_LANE], rx2[PER_LANE], ry2[PER_LANE];
        float rar[PER_LANE];
        int   rcl[PER_LANE];
#pragma unroll
        for (int t = 0; t < PER_LANE; t++) {
            int i = t * 32 + lane;
            if (i < cnt) {
                kk[t]  = skey[i];
                rx1[t] = sx1[i]; ry1[t] = sy1[i];
                rx2[t] = sx2[i]; ry2[t] = sy2[i];
                rar[t] = sar[i]; rcl[t] = scls[i];
            } else {
                kk[t] = 0; rcl[t] = -1;
                rx1[t] = ry1[t] = rx2[t] = ry2[t] = rar[t] = 0.f;
            }
        }

        for (int d = 0; d < MAXDET; d++) {
            // lane-local max key (+ slot)
            u64 bk = 0; int bs = 0;
#pragma unroll
            for (int t = 0; t < PER_LANE; t++)
                if (kk[t] > bk) { bk = kk[t]; bs = t; }

            unsigned hi  = (unsigned)(bk >> 32);
            unsigned mhi = __reduce_max_sync(0xffffffffu, hi);
            if (mhi == 0u) {                 // pool exhausted -> exact path
                if (lane == 0) sFallback = 1;
                break;
            }
            unsigned lo  = (hi == mhi) ? (unsigned)bk : 0u;
            unsigned mlo = __reduce_max_sync(0xffffffffu, lo);
            u64 selKey = ((u64)mhi << 32) | mlo;

            bool win = (bk == selKey);       // keys unique -> one winner
            unsigned wm = __ballot_sync(0xffffffffu, win);
            int wl   = __ffs(wm) - 1;
            int slot = __shfl_sync(0xffffffffu, bs, wl) * 32 + wl;

            float X1 = sx1[slot], Y1 = sy1[slot];    // broadcast LDS
            float X2 = sx2[slot], Y2 = sy2[slot];
            float AR = sar[slot];
            int   CL = scls[slot];

            if (lane == 0) {
                float* o = out + ((size_t)b * MAXDET + d) * 6;
                o[0] = scx[slot]; o[1] = scy[slot];
                o[2] = swd[slot]; o[3] = sht[slot];
                o[4] = (float)CL; o[5] = __uint_as_float(mhi);
            }
#pragma unroll
            for (int t = 0; t < PER_LANE; t++) {
                if (kk[t] == selKey) { kk[t] = 0; }
                else if (kk[t] != 0 && rcl[t] == CL) {
                    float iw = fminf(rx2[t], X2) - fmaxf(rx1[t], X1);
                    float ih = fminf(ry2[t], Y2) - fmaxf(ry1[t], Y1);
                    if (iw > 0.0f && ih > 0.0f) {
                        float inter = iw * ih;
                        float iou = inter / (rar[t] + AR - inter + 1e-8f);
                        if (iou > IOU_T) kk[t] = 0;
                    }
                }
            }
        }
    }
    __syncthreads();

    // ---------------- exact full-array fallback (normally unreachable) ----
    if (sFallback) {
        float* sc = g_scores + (size_t)b * A;
        const float4* bx = g_boxes8 + (size_t)b * A * 2;
        for (int d = 0; d < MAXDET; d++) {
            u64 mk = 0;
            for (int i = tid; i < A; i += NMS_NT) {
                u64 k = ((u64)__float_as_uint(sc[i]) << 32) |
                        (unsigned)(0x7FFFFFFF - i);
                if (k > mk) mk = k;
            }
#pragma unroll
            for (int off = 16; off; off >>= 1) {
                u64 ok = __shfl_down_sync(0xffffffffu, mk, off);
                if (ok > mk) mk = ok;
            }
            if ((tid & 31) == 0) redk[tid >> 5] = mk;
            __syncthreads();
            if (tid < 32) {
                u64 k2 = (tid < NMS_NT / 32) ? redk[tid] : 0ull;
#pragma unroll
                for (int off = 16; off; off >>= 1) {
                    u64 ok = __shfl_down_sync(0xffffffffu, k2, off);
                    if (ok > k2) k2 = ok;
                }
                if (tid == 0) sBest = k2;
            }
            __syncthreads();
            u64 selKey = sBest;
            int   a = 0x7FFFFFFF - (int)(selKey & 0xFFFFFFFFull);
            float selScore = __uint_as_float((unsigned)(selKey >> 32));
            float4 p0 = bx[(size_t)a * 2 + 0];
            float4 p1 = bx[(size_t)a * 2 + 1];
            float X1 = p0.x - 0.5f * p0.z, Y1 = p0.y - 0.5f * p0.w;
            float X2 = p0.x + 0.5f * p0.z, Y2 = p0.y + 0.5f * p0.w;
            float AR = p0.z * p0.w;
            int   CL = (int)p1.x;
            if (tid == 0) {
                float* o = out + ((size_t)b * MAXDET + d) * 6;
                o[0] = p0.x; o[1] = p0.y; o[2] = p0.z;
                o[3] = p0.w; o[4] = p1.x; o[5] = selScore;
            }
            __syncthreads();
            for (int i = tid; i < A; i += NMS_NT) {
                if (i == a) { sc[i] = 0.0f; continue; }
                if (sc[i] == 0.0f) continue;
                float4 q0 = bx[(size_t)i * 2 + 0];
                float4 q1 = bx[(size_t)i * 2 + 1];
                if ((int)q1.x == CL) {
                    float iw = fminf(q0.x + 0.5f * q0.z, X2) - fmaxf(q0.x - 0.5f * q0.z, X1);
                    float ih = fminf(q0.y + 0.5f * q0.w, Y2) - fmaxf(q0.y - 0.5f * q0.w, Y1);
                    if (iw > 0.0f && ih > 0.0f) {
                        float inter = iw * ih;
                        float iou = inter / (q0.z * q0.w + AR - inter + 1e-8f);
                        if (iou > IOU_T) sc[i] = 0.0f;
                    }
                }
            }
            __syncthreads();
        }
    }
}

// ---------------- launch ----------------
extern "C" void kernel_launch(void* const* d_in, const int* in_sizes, int n_in,
                              void* d_out, int out_size) {
    const float *pred, *anch;
    int s0 = in_sizes[0], s1 = in_sizes[1];
    if (s0 >= s1) {
        pred = (const float*)d_in[0]; anch = (const float*)d_in[1];
    } else {
        pred = (const float*)d_in[1]; anch = (const float*)d_in[0];
        int t = s0; s0 = s1; s1 = t;
    }
    int A = s1 / 4;
    int B = out_size / (MAXDET * 6);

    int totalWarps = B * A;
    decode_kernel<<<(totalWarps + 7) / 8, 256>>>(pred, anch, B, A);
    hist_compact_kernel<<<B, HT_NT>>>(A);
    nms_kernel<<<B, NMS_NT>>>((float*)d_out, A);
}

// round 6
// speedup vs baseline: 1.2098x; 1.0340x over previous
#include <cuda_runtime.h>

#define DPRED    84
#define NCLS     80
#define MAXB     8
#define MAXA     76725
#define NBINS    4096
#define KMAX     512
#define KTARGET  128
#define MAXDET   100
#define CONF_T   0.05f
#define IOU_T    0.5f
#define NMS_NT   256

typedef unsigned long long u64;

// ---------------- device scratch (no allocation allowed) ----------------
__device__ float4 g_boxes8[MAXB * MAXA * 2];  // cx,cy,w,h | cls,conf,0,0
__device__ float  g_scores[MAXB * MAXA];      // conf if >= CONF_T else 0
__device__ int    g_hist[MAXB * NBINS];
__device__ float  g_thresh[MAXB];
__device__ int    g_cnt[MAXB];
__device__ int    g_cand[MAXB * KMAX];

// order-preserving float -> u32 key
__device__ __forceinline__ unsigned fkey(float f) {
    unsigned u = __float_as_uint(f);
    return u ^ (unsigned)(((int)u >> 31) | 0x80000000);
}

// ---------------- zero hist ----------------
__global__ void zero_hist_kernel(int n) {
    int i = blockIdx.x * blockDim.x + threadIdx.x;
    if (i < n) g_hist[i] = 0;
}

// ---------------- decode: warp per anchor, REDUX argmax ----------------
__global__ void decode_kernel(const float* __restrict__ pred,
                              const float* __restrict__ anchors,
                              int B, int A) {
    int gw   = (blockIdx.x * blockDim.x + threadIdx.x) >> 5;
    int lane = threadIdx.x & 31;
    if (gw >= B * A) return;

    const float4* row = reinterpret_cast<const float4*>(pred + (size_t)gw * DPRED);
    float4 v = make_float4(0.f, 0.f, 0.f, 0.f);
    if (lane < DPRED / 4)
        v = __ldg(row + lane);

    // sortable keys; lane 0 holds box fields (excluded), lanes >= 21 idle
    unsigned k0 = fkey(v.x), k1 = fkey(v.y), k2 = fkey(v.z), k3 = fkey(v.w);
    if (lane == 0 || lane >= DPRED / 4) { k0 = k1 = k2 = k3 = 0u; }

    // branchless lane-local max, first-occurrence wins (strict >)
    unsigned bk = k0; int bt = 0;
    if (k1 > bk) { bk = k1; bt = 1; }
    if (k2 > bk) { bk = k2; bt = 2; }
    if (k3 > bk) { bk = k3; bt = 3; }

    unsigned mhi = __reduce_max_sync(0xffffffffu, bk);
    int myidx = lane * 4 + bt - 4;                      // class index
    unsigned lo  = (bk == mhi) ? (unsigned)(255 - myidx) : 0u;
    unsigned mlo = __reduce_max_sync(0xffffffffu, lo);

    if (lane == 0) {
        int b = gw / A;
        int a = gw - b * A;
        int cls = 255 - (int)mlo;
        unsigned bits = (mhi & 0x80000000u) ? (mhi ^ 0x80000000u) : ~mhi;
        float best = __uint_as_float(bits);
        float conf = 1.0f / (1.0f + expf(-best));

        float4 an = __ldg(reinterpret_cast<const float4*>(anchors) + a);
        float cx = v.x * 0.1f * an.z + an.x;
        float cy = v.y * 0.1f * an.w + an.y;
        float w  = expf(v.z * 0.2f) * an.z;
        float h  = expf(v.w * 0.2f) * an.w;

        g_boxes8[(size_t)gw * 2 + 0] = make_float4(cx, cy, w, h);
        g_boxes8[(size_t)gw * 2 + 1] = make_float4((float)cls, conf, 0.f, 0.f);

        float s = (conf >= CONF_T) ? conf : 0.0f;
        g_scores[gw] = s;
        if (s > 0.0f) {
            int bin = (int)(s * (float)NBINS);
            if (bin > NBINS - 1) bin = NBINS - 1;
            if (bin < 1) bin = 1;
            atomicAdd(&g_hist[b * NBINS + bin], 1);
        }
    }
}

// ---------------- threshold from histogram: one small block per batch ----
__global__ void __launch_bounds__(128)
thresh_kernel() {
    int b   = blockIdx.x;
    int tid = threadIdx.x;
    __shared__ int sh[NBINS];
    __shared__ int csum[128];          // 32-bin chunk sums

    for (int i = tid; i < NBINS; i += 128)
        sh[i] = g_hist[b * NBINS + i];
    __syncthreads();

    {
        int s = 0, base = tid * 32;
#pragma unroll
        for (int j = 0; j < 32; j++) s += sh[base + j];
        csum[tid] = s;
    }
    __syncthreads();

    if (tid == 0) {
        int cum = 0, binSel = NBINS, c = 128;
        while (c > 1 && cum < KTARGET && cum + csum[c - 1] <= KMAX) {
            c--; cum += csum[c]; binSel = c * 32;
        }
        if (cum < KTARGET && c >= 1) {
            for (int bin = c * 32 - 1; bin >= (c - 1) * 32 && bin >= 1; --bin) {
                int h = sh[bin];
                if (cum + h > KMAX) break;
                cum += h; binSel = bin;
                if (cum >= KTARGET) break;
            }
        }
        g_thresh[b] = (float)binSel / (float)NBINS;
        g_cnt[b]    = 0;
    }
}

// ---------------- compact candidates: many blocks per batch ----------------
__global__ void compact_kernel(int A) {
    int b = blockIdx.y;
    float th = g_thresh[b];
    const float* sc = g_scores + (size_t)b * A;
    for (int i = blockIdx.x * blockDim.x + threadIdx.x; i < A;
         i += gridDim.x * blockDim.x) {
        if (sc[i] > th) {
            int p = atomicAdd(&g_cnt[b], 1);
            if (p < KMAX) g_cand[b * KMAX + p] = i;
        }
    }
}

// ---------------- NMS: block per batch, warp-0 smem scan + REDUX --------
__global__ void __launch_bounds__(NMS_NT, 1)
nms_kernel(float* __restrict__ out, int A) {
    int b   = blockIdx.x;
    int tid = threadIdx.x;

    __shared__ u64   skey[KMAX];
    __shared__ float sx1[KMAX], sy1[KMAX], sx2[KMAX], sy2[KMAX], sar[KMAX];
    __shared__ float scx[KMAX], scy[KMAX], swd[KMAX], sht[KMAX];
    __shared__ int   scls[KMAX];
    __shared__ int   sFallback;
    __shared__ u64   sBest;
    __shared__ u64   redk[NMS_NT / 32];

    int cnt = g_cnt[b];
    bool overflow = (cnt > KMAX);
    if (cnt > KMAX) cnt = KMAX;

    for (int i = tid; i < cnt; i += NMS_NT) {
        int a = g_cand[b * KMAX + i];
        size_t base = ((size_t)b * A + a) * 2;
        float4 p0 = g_boxes8[base + 0];
        float4 p1 = g_boxes8[base + 1];
        float hw = 0.5f * p0.z, hh = 0.5f * p0.w;
        sx1[i] = p0.x - hw; sy1[i] = p0.y - hh;
        sx2[i] = p0.x + hw; sy2[i] = p0.y + hh;
        sar[i] = p0.z * p0.w;
        scx[i] = p0.x; scy[i] = p0.y; swd[i] = p0.z; sht[i] = p0.w;
        scls[i] = (int)p1.x;
        skey[i] = ((u64)__float_as_uint(p1.y) << 32) |
                  (unsigned)(0x7FFFFFFF - a);
    }
    if (tid == 0) sFallback = overflow ? 1 : 0;
    __syncthreads();

    // ---- fast path: warp 0 only, no block barriers, no atomics ----
    if (tid < 32 && !sFallback) {
        int lane = tid;
        for (int d = 0; d < MAXDET; d++) {
            u64 bk = 0; int bs = 0;
            for (int i = lane; i < cnt; i += 32) {
                u64 k = skey[i];
                if (k > bk) { bk = k; bs = i; }
            }
            unsigned hi  = (unsigned)(bk >> 32);
            unsigned mhi = __reduce_max_sync(0xffffffffu, hi);
            if (mhi == 0u) {                 // pool exhausted -> exact path
                if (lane == 0) sFallback = 1;
                break;
            }
            unsigned lo  = (hi == mhi) ? (unsigned)bk : 0u;
            unsigned mlo = __reduce_max_sync(0xffffffffu, lo);
            u64 selKey = ((u64)mhi << 32) | mlo;

            bool win = (bk == selKey);       // keys unique -> one winner
            unsigned wm = __ballot_sync(0xffffffffu, win);
            int wl   = __ffs(wm) - 1;
            int slot = __shfl_sync(0xffffffffu, bs, wl);

            float X1 = sx1[slot], Y1 = sy1[slot];    // broadcast LDS
            float X2 = sx2[slot], Y2 = sy2[slot];
            float AR = sar[slot];
            int   CL = scls[slot];

            if (lane == 0) {
                float* o = out + ((size_t)b * MAXDET + d) * 6;
                o[0] = scx[slot]; o[1] = scy[slot];
                o[2] = swd[slot]; o[3] = sht[slot];
                o[4] = (float)CL; o[5] = __uint_as_float(mhi);
            }
            for (int i = lane; i < cnt; i += 32) {
                u64 k = skey[i];
                if (k == selKey) { skey[i] = 0; continue; }
                if (k != 0 && scls[i] == CL) {
                    float iw = fminf(sx2[i], X2) - fmaxf(sx1[i], X1);
                    float ih = fminf(sy2[i], Y2) - fmaxf(sy1[i], Y1);
                    if (iw > 0.0f && ih > 0.0f) {
                        float inter = iw * ih;
                        float iou = inter / (sar[i] + AR - inter + 1e-8f);
                        if (iou > IOU_T) skey[i] = 0;
                    }
                }
            }
            __syncwarp();
        }
    }
    __syncthreads();

    // ---------------- exact full-array fallback (normally unreachable) ----
    if (sFallback) {
        float* sc = g_scores + (size_t)b * A;
        const float4* bx = g_boxes8 + (size_t)b * A * 2;
        for (int d = 0; d < MAXDET; d++) {
            u64 mk = 0;
            for (int i = tid; i < A; i += NMS_NT) {
                u64 k = ((u64)__float_as_uint(sc[i]) << 32) |
                        (unsigned)(0x7FFFFFFF - i);
                if (k > mk) mk = k;
            }
#pragma unroll
            for (int off = 16; off; off >>= 1) {
                u64 ok = __shfl_down_sync(0xffffffffu, mk, off);
                if (ok > mk) mk = ok;
            }
            if ((tid & 31) == 0) redk[tid >> 5] = mk;
            __syncthreads();
            if (tid < 32) {
                u64 k2 = (tid < NMS_NT / 32) ? redk[tid] : 0ull;
#pragma unroll
                for (int off = 16; off; off >>= 1) {
                    u64 ok = __shfl_down_sync(0xffffffffu, k2, off);
                    if (ok > k2) k2 = ok;
                }
                if (tid == 0) sBest = k2;
            }
            __syncthreads();
            u64 selKey = sBest;
            int   a = 0x7FFFFFFF - (int)(selKey & 0xFFFFFFFFull);
            float selScore = __uint_as_float((unsigned)(selKey >> 32));
            float4 p0 = bx[(size_t)a * 2 + 0];
            float4 p1 = bx[(size_t)a * 2 + 1];
            float X1 = p0.x - 0.5f * p0.z, Y1 = p0.y - 0.5f * p0.w;
            float X2 = p0.x + 0.5f * p0.z, Y2 = p0.y + 0.5f * p0.w;
            float AR = p0.z * p0.w;
            int   CL = (int)p1.x;
            if (tid == 0) {
                float* o = out + ((size_t)b * MAXDET + d) * 6;
                o[0] = p0.x; o[1] = p0.y; o[2] = p0.z;
                o[3] = p0.w; o[4] = p1.x; o[5] = selScore;
            }
            __syncthreads();
            for (int i = tid; i < A; i += NMS_NT) {
                if (i == a) { sc[i] = 0.0f; continue; }
                if (sc[i] == 0.0f) continue;
                float4 q0 = bx[(size_t)i * 2 + 0];
                float4 q1 = bx[(size_t)i * 2 + 1];
                if ((int)q1.x == CL) {
                    float iw = fminf(q0.x + 0.5f * q0.z, X2) - fmaxf(q0.x - 0.5f * q0.z, X1);
                    float ih = fminf(q0.y + 0.5f * q0.w, Y2) - fmaxf(q0.y - 0.5f * q0.w, Y1);
                    if (iw > 0.0f && ih > 0.0f) {
                        float inter = iw * ih;
                        float iou = inter / (q0.z * q0.w + AR - inter + 1e-8f);
                        if (iou > IOU_T) sc[i] = 0.0f;
                    }
                }
            }
            __syncthreads();
        }
    }
}

// ---------------- launch ----------------
extern "C" void kernel_launch(void* const* d_in, const int* in_sizes, int n_in,
                              void* d_out, int out_size) {
    const float *pred, *anch;
    int s0 = in_sizes[0], s1 = in_sizes[1];
    if (s0 >= s1) {
        pred = (const float*)d_in[0]; anch = (const float*)d_in[1];
    } else {
        pred = (const float*)d_in[1]; anch = (const float*)d_in[0];
        int t = s0; s0 = s1; s1 = t;
    }
    int A = s1 / 4;
    int B = out_size / (MAXDET * 6);

    int totalWarps = B * A;
    zero_hist_kernel<<<(B * NBINS + 255) / 256, 256>>>(B * NBINS);
    decode_kernel<<<(totalWarps + 7) / 8, 256>>>(pred, anch, B, A);
    thresh_kernel<<<B, 128>>>();
    compact_kernel<<<dim3(16, B), 256>>>(A);
    nms_kernel<<<B, NMS_NT>>>((float*)d_out, A);
}

// round 7
// speedup vs baseline: 1.5839x; 1.3093x over previous
#include <cuda_runtime.h>

#define DPRED    84
#define NCLS     80
#define MAXB     8
#define MAXA     76725
#define NBINS    4096
#define KMAX     512
#define KTARGET  128
#define MAXDET   100
#define CONF_T   0.05f
#define IOU_T    0.5f
#define NMS_NT   256

typedef unsigned long long u64;

// ---------------- device scratch (no allocation allowed) ----------------
__device__ float4 g_boxes8[MAXB * MAXA * 2];  // cx,cy,w,h | cls,conf,0,0
__device__ float  g_scores[MAXB * MAXA];      // conf if >= CONF_T else 0
__device__ int    g_hist[MAXB * NBINS];
__device__ float  g_thresh[MAXB];
__device__ int    g_cnt[MAXB];
__device__ int    g_cand[MAXB * KMAX];

// ---------------- zero hist ----------------
__global__ void zero_hist_kernel(int n) {
    int i = blockIdx.x * blockDim.x + threadIdx.x;
    if (i < n) g_hist[i] = 0;
}

// ---------------- decode: THREAD per anchor ----------------
__global__ void __launch_bounds__(256)
decode_kernel(const float* __restrict__ pred,
              const float* __restrict__ anchors,
              int B, int A) {
    int i = blockIdx.x * blockDim.x + threadIdx.x;
    if (i >= B * A) return;

    const float4* row = reinterpret_cast<const float4*>(pred + (size_t)i * DPRED);

    float4 v0 = __ldg(row + 0);                 // box preds

    // branchless first-occurrence argmax over 80 class logits
    float best = -3.4e38f;
    int   cls  = 0;
#pragma unroll
    for (int j = 1; j <= 20; j++) {
        float4 c = __ldg(row + j);
        int base = (j - 1) * 4;
        if (c.x > best) { best = c.x; cls = base + 0; }
        if (c.y > best) { best = c.y; cls = base + 1; }
        if (c.z > best) { best = c.z; cls = base + 2; }
        if (c.w > best) { best = c.w; cls = base + 3; }
    }

    int b = i / A;
    int a = i - b * A;

    float4 an = __ldg(reinterpret_cast<const float4*>(anchors) + a);
    float cx = v0.x * 0.1f * an.z + an.x;
    float cy = v0.y * 0.1f * an.w + an.y;
    float w  = expf(v0.z * 0.2f) * an.z;
    float h  = expf(v0.w * 0.2f) * an.w;
    float conf = 1.0f / (1.0f + expf(-best));

    g_boxes8[(size_t)i * 2 + 0] = make_float4(cx, cy, w, h);
    g_boxes8[(size_t)i * 2 + 1] = make_float4((float)cls, conf, 0.f, 0.f);

    float s = (conf >= CONF_T) ? conf : 0.0f;
    g_scores[i] = s;
    if (s > 0.0f) {
        int bin = (int)(s * (float)NBINS);
        if (bin > NBINS - 1) bin = NBINS - 1;
        if (bin < 1) bin = 1;
        atomicAdd(&g_hist[b * NBINS + bin], 1);
    }
}

// ---------------- threshold from histogram: one block per batch ----------
__global__ void __launch_bounds__(512)
thresh_kernel() {
    int b   = blockIdx.x;
    int tid = threadIdx.x;
    __shared__ int sh[NBINS];
    __shared__ int csum[128];          // 32-bin chunk sums

    for (int i = tid; i < NBINS; i += 512)
        sh[i] = __ldg(&g_hist[b * NBINS + i]);
    __syncthreads();

    if (tid < 128) {
        int s = 0, base = tid * 32;
#pragma unroll
        for (int j = 0; j < 32; j++) s += sh[base + j];
        csum[tid] = s;
    }
    __syncthreads();

    if (tid == 0) {
        int cum = 0, binSel = NBINS, c = 128;
        while (c > 1 && cum < KTARGET && cum + csum[c - 1] <= KMAX) {
            c--; cum += csum[c]; binSel = c * 32;
        }
        if (cum < KTARGET && c >= 1) {
            for (int bin = c * 32 - 1; bin >= (c - 1) * 32 && bin >= 1; --bin) {
                int h = sh[bin];
                if (cum + h > KMAX) break;
                cum += h; binSel = bin;
                if (cum >= KTARGET) break;
            }
        }
        g_thresh[b] = (float)binSel / (float)NBINS;
        g_cnt[b]    = 0;
    }
}

// ---------------- compact candidates: many blocks per batch --------------
__global__ void compact_kernel(int A) {
    int b = blockIdx.y;
    float th = g_thresh[b];
    const float* sc = g_scores + (size_t)b * A;
    for (int i = blockIdx.x * blockDim.x + threadIdx.x; i < A;
         i += gridDim.x * blockDim.x) {
        if (sc[i] > th) {
            int p = atomicAdd(&g_cnt[b], 1);
            if (p < KMAX) g_cand[b * KMAX + p] = i;
        }
    }
}

// ---------------- NMS: block per batch, warp-0 smem scan + REDUX --------
__global__ void __launch_bounds__(NMS_NT, 1)
nms_kernel(float* __restrict__ out, int A) {
    int b   = blockIdx.x;
    int tid = threadIdx.x;

    __shared__ u64   skey[KMAX];
    __shared__ float sx1[KMAX], sy1[KMAX], sx2[KMAX], sy2[KMAX], sar[KMAX];
    __shared__ float scx[KMAX], scy[KMAX], swd[KMAX], sht[KMAX];
    __shared__ int   scls[KMAX];
    __shared__ int   sFallback;
    __shared__ u64   sBest;
    __shared__ u64   redk[NMS_NT / 32];

    int cnt = g_cnt[b];
    bool overflow = (cnt > KMAX);
    if (cnt > KMAX) cnt = KMAX;

    for (int i = tid; i < cnt; i += NMS_NT) {
        int a = g_cand[b * KMAX + i];
        size_t base = ((size_t)b * A + a) * 2;
        float4 p0 = g_boxes8[base + 0];
        float4 p1 = g_boxes8[base + 1];
        float hw = 0.5f * p0.z, hh = 0.5f * p0.w;
        sx1[i] = p0.x - hw; sy1[i] = p0.y - hh;
        sx2[i] = p0.x + hw; sy2[i] = p0.y + hh;
        sar[i] = p0.z * p0.w;
        scx[i] = p0.x; scy[i] = p0.y; swd[i] = p0.z; sht[i] = p0.w;
        scls[i] = (int)p1.x;
        skey[i] = ((u64)__float_as_uint(p1.y) << 32) |
                  (unsigned)(0x7FFFFFFF - a);
    }
    if (tid == 0) sFallback = overflow ? 1 : 0;
    __syncthreads();

    // ---- fast path: warp 0 only, no block barriers, no atomics ----
    if (tid < 32 && !sFallback) {
        int lane = tid;
        for (int d = 0; d < MAXDET; d++) {
            u64 bk = 0; int bs = 0;
            for (int i = lane; i < cnt; i += 32) {
                u64 k = skey[i];
                if (k > bk) { bk = k; bs = i; }
            }
            unsigned hi  = (unsigned)(bk >> 32);
            unsigned mhi = __reduce_max_sync(0xffffffffu, hi);
            if (mhi == 0u) {                 // pool exhausted -> exact path
                if (lane == 0) sFallback = 1;
                break;
            }
            unsigned lo  = (hi == mhi) ? (unsigned)bk : 0u;
            unsigned mlo = __reduce_max_sync(0xffffffffu, lo);
            u64 selKey = ((u64)mhi << 32) | mlo;

            bool win = (bk == selKey);       // keys unique -> one winner
            unsigned wm = __ballot_sync(0xffffffffu, win);
            int wl   = __ffs(wm) - 1;
            int slot = __shfl_sync(0xffffffffu, bs, wl);

            float X1 = sx1[slot], Y1 = sy1[slot];    // broadcast LDS
            float X2 = sx2[slot], Y2 = sy2[slot];
            float AR = sar[slot];
            int   CL = scls[slot];

            if (lane == 0) {
                float* o = out + ((size_t)b * MAXDET + d) * 6;
                o[0] = scx[slot]; o[1] = scy[slot];
                o[2] = swd[slot]; o[3] = sht[slot];
                o[4] = (float)CL; o[5] = __uint_as_float(mhi);
            }
            for (int i = lane; i < cnt; i += 32) {
                u64 k = skey[i];
                if (k == selKey) { skey[i] = 0; continue; }
                if (k != 0 && scls[i] == CL) {
                    float iw = fminf(sx2[i], X2) - fmaxf(sx1[i], X1);
                    float ih = fminf(sy2[i], Y2) - fmaxf(sy1[i], Y1);
                    if (iw > 0.0f && ih > 0.0f) {
                        float inter = iw * ih;
                        float iou = inter / (sar[i] + AR - inter + 1e-8f);
                        if (iou > IOU_T) skey[i] = 0;
                    }
                }
            }
            __syncwarp();
        }
    }
    __syncthreads();

    // ---------------- exact full-array fallback (normally unreachable) ----
    if (sFallback) {
        float* sc = g_scores + (size_t)b * A;
        const float4* bx = g_boxes8 + (size_t)b * A * 2;
        for (int d = 0; d < MAXDET; d++) {
            u64 mk = 0;
            for (int i = tid; i < A; i += NMS_NT) {
                u64 k = ((u64)__float_as_uint(sc[i]) << 32) |
                        (unsigned)(0x7FFFFFFF - i);
                if (k > mk) mk = k;
            }
#pragma unroll
            for (int off = 16; off; off >>= 1) {
                u64 ok = __shfl_down_sync(0xffffffffu, mk, off);
                if (ok > mk) mk = ok;
            }
            if ((tid & 31) == 0) redk[tid >> 5] = mk;
            __syncthreads();
            if (tid < 32) {
                u64 k2 = (tid < NMS_NT / 32) ? redk[tid] : 0ull;
#pragma unroll
                for (int off = 16; off; off >>= 1) {
                    u64 ok = __shfl_down_sync(0xffffffffu, k2, off);
                    if (ok > k2) k2 = ok;
                }
                if (tid == 0) sBest = k2;
            }
            __syncthreads();
            u64 selKey = sBest;
            int   a = 0x7FFFFFFF - (int)(selKey & 0xFFFFFFFFull);
            float selScore = __uint_as_float((unsigned)(selKey >> 32));
            float4 p0 = bx[(size_t)a * 2 + 0];
            float4 p1 = bx[(size_t)a * 2 + 1];
            float X1 = p0.x - 0.5f * p0.z, Y1 = p0.y - 0.5f * p0.w;
            float X2 = p0.x + 0.5f * p0.z, Y2 = p0.y + 0.5f * p0.w;
            float AR = p0.z * p0.w;
            int   CL = (int)p1.x;
            if (tid == 0) {
                float* o = out + ((size_t)b * MAXDET + d) * 6;
                o[0] = p0.x; o[1] = p0.y; o[2] = p0.z;
                o[3] = p0.w; o[4] = p1.x; o[5] = selScore;
            }
            __syncthreads();
            for (int i = tid; i < A; i += NMS_NT) {
                if (i == a) { sc[i] = 0.0f; continue; }
                if (sc[i] == 0.0f) continue;
                float4 q0 = bx[(size_t)i * 2 + 0];
                float4 q1 = bx[(size_t)i * 2 + 1];
                if ((int)q1.x == CL) {
                    float iw = fminf(q0.x + 0.5f * q0.z, X2) - fmaxf(q0.x - 0.5f * q0.z, X1);
                    float ih = fminf(q0.y + 0.5f * q0.w, Y2) - fmaxf(q0.y - 0.5f * q0.w, Y1);
                    if (iw > 0.0f && ih > 0.0f) {
                        float inter = iw * ih;
                        float iou = inter / (q0.z * q0.w + AR - inter + 1e-8f);
                        if (iou > IOU_T) sc[i] = 0.0f;
                    }
                }
            }
            __syncthreads();
        }
    }
}

// ---------------- launch ----------------
extern "C" void kernel_launch(void* const* d_in, const int* in_sizes, int n_in,
                              void* d_out, int out_size) {
    const float *pred, *anch;
    int s0 = in_sizes[0], s1 = in_sizes[1];
    if (s0 >= s1) {
        pred = (const float*)d_in[0]; anch = (const float*)d_in[1];
    } else {
        pred = (const float*)d_in[1]; anch = (const float*)d_in[0];
        int t = s0; s0 = s1; s1 = t;
    }
    int A = s1 / 4;
    int B = out_size / (MAXDET * 6);

    int total = B * A;
    zero_hist_kernel<<<(B * NBINS + 255) / 256, 256>>>(B * NBINS);
    decode_kernel<<<(total + 255) / 256, 256>>>(pred, anch, B, A);
    thresh_kernel<<<B, 512>>>();
    compact_kernel<<<dim3(32, B), 256>>>(A);
    nms_kernel<<<B, NMS_NT>>>((float*)d_out, A);
}